// round 2
// baseline (speedup 1.0000x reference)
#include <cuda_runtime.h>
#include <cuda_bf16.h>
#include <math.h>

// Problem constants
#define T_TOK   2048      // B*S
#define H_DIM   1024
#define I_DIM   512
#define N_EXP   32
#define TOP_K   4
#define N_GROUP 4
#define GRP_SZ  8         // E / N_GROUP
#define TOPK_GROUP 2
#define SCALE   2.5f
#define SH_I    1024

// GEMM tiling
#define BM 64
#define BN 64
#define BK 16
#define NTHREADS 256

// ---------------- scratch (device globals; no allocation allowed) ------------
__device__ float g_hidden[(size_t)N_EXP * T_TOK * I_DIM];   // routed SwiGLU hidden
__device__ float g_hidden_sh[(size_t)T_TOK * SH_I];          // shared-expert hidden
__device__ int   g_counts[N_EXP];
__device__ int   g_tok[N_EXP * T_TOK];
__device__ float g_wt[N_EXP * T_TOK];

// ---------------------------------------------------------------------------
__global__ void zero_counts_kernel() {
    if (threadIdx.x < N_EXP) g_counts[threadIdx.x] = 0;
}

// One warp per token: lane e computes logit for expert e. The shuffle gather is
// warp-collective (ALL lanes execute it); only the scalar top-k runs on lane 0.
__global__ void router_kernel(const float* __restrict__ hs,
                              const float* __restrict__ rw,
                              const float* __restrict__ rb) {
    int warp = threadIdx.x >> 5;
    int lane = threadIdx.x & 31;
    int t = blockIdx.x * (blockDim.x >> 5) + warp;
    if (t >= T_TOK) return;   // grid exactly covers T_TOK; whole warps only

    const float* x = hs + (size_t)t * H_DIM;
    const float* w = rw + (size_t)lane * H_DIM;

    float a0 = 0.f, a1 = 0.f, a2 = 0.f, a3 = 0.f;
    #pragma unroll 4
    for (int h = 0; h < H_DIM; h += 4) {
        a0 = fmaf(x[h + 0], w[h + 0], a0);
        a1 = fmaf(x[h + 1], w[h + 1], a1);
        a2 = fmaf(x[h + 2], w[h + 2], a2);
        a3 = fmaf(x[h + 3], w[h + 3], a3);
    }
    float logit = (a0 + a1) + (a2 + a3);
    float score = 1.f / (1.f + expf(-logit));   // sigmoid
    float sfc   = score + rb[lane];

    // warp-collective gather: every lane participates in every shuffle
    float s[N_EXP], sc[N_EXP];
    #pragma unroll
    for (int e = 0; e < N_EXP; e++) {
        s[e]  = __shfl_sync(0xffffffffu, sfc, e);
        sc[e] = __shfl_sync(0xffffffffu, score, e);
    }

    if (lane == 0) {
        // group scores = sum of top-2 within each group of 8
        float gsc[N_GROUP];
        #pragma unroll
        for (int g = 0; g < N_GROUP; g++) {
            float m1 = -1e30f, m2 = -1e30f;
            #pragma unroll
            for (int j = 0; j < GRP_SZ; j++) {
                float v = s[g * GRP_SZ + j];
                if (v > m1) { m2 = m1; m1 = v; }
                else if (v > m2) { m2 = v; }
            }
            gsc[g] = m1 + m2;
        }
        // top-2 groups (ties -> lower index, matching lax.top_k)
        int g1 = 0;
        #pragma unroll
        for (int g = 1; g < N_GROUP; g++) if (gsc[g] > gsc[g1]) g1 = g;
        int g2 = -1;
        #pragma unroll
        for (int g = 0; g < N_GROUP; g++) {
            if (g == g1) continue;
            if (g2 < 0 || gsc[g] > gsc[g2]) g2 = g;
        }
        // masked scores (reference uses 0.0 for masked; sigmoid>0 so -1e30 equiv)
        float v[N_EXP];
        #pragma unroll
        for (int e = 0; e < N_EXP; e++) {
            int g = e / GRP_SZ;
            v[e] = (g == g1 || g == g2) ? s[e] : -1e30f;
        }
        // top-4 of masked
        int   idx[TOP_K];
        float wsum = 0.f;
        #pragma unroll
        for (int k = 0; k < TOP_K; k++) {
            int b = 0;
            #pragma unroll
            for (int e = 1; e < N_EXP; e++) if (v[e] > v[b]) b = e;
            idx[k] = b;
            v[b] = -2e30f;
            wsum += sc[b];
        }
        float inv = SCALE / (wsum + 1e-20f);
        #pragma unroll
        for (int k = 0; k < TOP_K; k++) {
            int e = idx[k];
            int p = atomicAdd(&g_counts[e], 1);
            g_tok[e * T_TOK + p] = t;
            g_wt [e * T_TOK + p] = sc[e] * inv;
        }
    }
}

// ---------------------------------------------------------------------------
// Expert gate+up: for expert e, rows = gathered tokens, N = I_DIM, K = H_DIM.
// hidden = silu(x @ gate^T) * (x @ up^T)  -> g_hidden[e][row][n]
__global__ __launch_bounds__(NTHREADS)
void expert_gateup_kernel(const float* __restrict__ X,
                          const float* __restrict__ GW,
                          const float* __restrict__ UW) {
    int e   = blockIdx.z;
    int cnt = g_counts[e];
    int m0  = blockIdx.y * BM;
    if (m0 >= cnt) return;
    int n0  = blockIdx.x * BN;

    __shared__ float As[BK][BM + 4];
    __shared__ float Gs[BK][BN + 4];
    __shared__ float Us[BK][BN + 4];

    int tid  = threadIdx.x;
    int tx   = tid & 15;          // N
    int ty   = tid >> 4;          // M
    int lrow = tid >> 2;          // 0..63 load row
    int lk   = (tid & 3) * 4;     // 0,4,8,12

    int r = m0 + lrow;
    int tokrow = g_tok[e * T_TOK + ((r < cnt) ? r : (cnt - 1))];
    const float* arow = X + (size_t)tokrow * H_DIM;
    const float* grow = GW + ((size_t)e * I_DIM + (n0 + lrow)) * H_DIM;
    const float* urow = UW + ((size_t)e * I_DIM + (n0 + lrow)) * H_DIM;

    float accG[4][4] = {{0}}, accU[4][4] = {{0}};

    for (int k0 = 0; k0 < H_DIM; k0 += BK) {
        float4 av = *(const float4*)(arow + k0 + lk);
        float4 gv = *(const float4*)(grow + k0 + lk);
        float4 uv = *(const float4*)(urow + k0 + lk);
        As[lk+0][lrow] = av.x; As[lk+1][lrow] = av.y; As[lk+2][lrow] = av.z; As[lk+3][lrow] = av.w;
        Gs[lk+0][lrow] = gv.x; Gs[lk+1][lrow] = gv.y; Gs[lk+2][lrow] = gv.z; Gs[lk+3][lrow] = gv.w;
        Us[lk+0][lrow] = uv.x; Us[lk+1][lrow] = uv.y; Us[lk+2][lrow] = uv.z; Us[lk+3][lrow] = uv.w;
        __syncthreads();
        #pragma unroll
        for (int kk = 0; kk < BK; kk++) {
            float a[4], g[4], u[4];
            *(float4*)a = *(const float4*)&As[kk][ty * 4];
            *(float4*)g = *(const float4*)&Gs[kk][tx * 4];
            *(float4*)u = *(const float4*)&Us[kk][tx * 4];
            #pragma unroll
            for (int i = 0; i < 4; i++)
                #pragma unroll
                for (int j = 0; j < 4; j++) {
                    accG[i][j] = fmaf(a[i], g[j], accG[i][j]);
                    accU[i][j] = fmaf(a[i], u[j], accU[i][j]);
                }
        }
        __syncthreads();
    }

    #pragma unroll
    for (int i = 0; i < 4; i++) {
        int rr = m0 + ty * 4 + i;
        if (rr >= cnt) continue;
        float* hb = g_hidden + ((size_t)e * T_TOK + rr) * I_DIM + n0 + tx * 4;
        #pragma unroll
        for (int j = 0; j < 4; j++) {
            float gval = accG[i][j];
            float sil  = gval / (1.f + expf(-gval));
            hb[j] = sil * accU[i][j];
        }
    }
}

// Expert down: out[t][h] += wt * (hidden[e][row] . down_w[e][h])
__global__ __launch_bounds__(NTHREADS)
void expert_down_kernel(const float* __restrict__ DW, float* __restrict__ out) {
    int e   = blockIdx.z;
    int cnt = g_counts[e];
    int m0  = blockIdx.y * BM;
    if (m0 >= cnt) return;
    int n0  = blockIdx.x * BN;   // over H

    __shared__ float As[BK][BM + 4];
    __shared__ float Bs[BK][BN + 4];

    int tid  = threadIdx.x;
    int tx   = tid & 15;
    int ty   = tid >> 4;
    int lrow = tid >> 2;
    int lk   = (tid & 3) * 4;

    int r = m0 + lrow;
    int rcl = (r < cnt) ? r : (cnt - 1);
    const float* arow = g_hidden + ((size_t)e * T_TOK + rcl) * I_DIM;
    const float* brow = DW + ((size_t)e * H_DIM + (n0 + lrow)) * I_DIM;

    float acc[4][4] = {{0}};
    for (int k0 = 0; k0 < I_DIM; k0 += BK) {
        float4 av = *(const float4*)(arow + k0 + lk);
        float4 bv = *(const float4*)(brow + k0 + lk);
        As[lk+0][lrow] = av.x; As[lk+1][lrow] = av.y; As[lk+2][lrow] = av.z; As[lk+3][lrow] = av.w;
        Bs[lk+0][lrow] = bv.x; Bs[lk+1][lrow] = bv.y; Bs[lk+2][lrow] = bv.z; Bs[lk+3][lrow] = bv.w;
        __syncthreads();
        #pragma unroll
        for (int kk = 0; kk < BK; kk++) {
            float a[4], b[4];
            *(float4*)a = *(const float4*)&As[kk][ty * 4];
            *(float4*)b = *(const float4*)&Bs[kk][tx * 4];
            #pragma unroll
            for (int i = 0; i < 4; i++)
                #pragma unroll
                for (int j = 0; j < 4; j++)
                    acc[i][j] = fmaf(a[i], b[j], acc[i][j]);
        }
        __syncthreads();
    }

    #pragma unroll
    for (int i = 0; i < 4; i++) {
        int rr = m0 + ty * 4 + i;
        if (rr >= cnt) continue;
        int   tok = g_tok[e * T_TOK + rr];
        float wt  = g_wt [e * T_TOK + rr];
        float* op = out + (size_t)tok * H_DIM + n0 + tx * 4;
        #pragma unroll
        for (int j = 0; j < 4; j++)
            atomicAdd(&op[j], acc[i][j] * wt);
    }
}

// ---------------------------------------------------------------------------
// Shared experts: dense over all T tokens.
__global__ __launch_bounds__(NTHREADS)
void shared_gateup_kernel(const float* __restrict__ X,
                          const float* __restrict__ GW,
                          const float* __restrict__ UW) {
    int m0 = blockIdx.y * BM;
    int n0 = blockIdx.x * BN;   // over SH_I

    __shared__ float As[BK][BM + 4];
    __shared__ float Gs[BK][BN + 4];
    __shared__ float Us[BK][BN + 4];

    int tid  = threadIdx.x;
    int tx   = tid & 15;
    int ty   = tid >> 4;
    int lrow = tid >> 2;
    int lk   = (tid & 3) * 4;

    const float* arow = X  + (size_t)(m0 + lrow) * H_DIM;
    const float* grow = GW + (size_t)(n0 + lrow) * H_DIM;
    const float* urow = UW + (size_t)(n0 + lrow) * H_DIM;

    float accG[4][4] = {{0}}, accU[4][4] = {{0}};
    for (int k0 = 0; k0 < H_DIM; k0 += BK) {
        float4 av = *(const float4*)(arow + k0 + lk);
        float4 gv = *(const float4*)(grow + k0 + lk);
        float4 uv = *(const float4*)(urow + k0 + lk);
        As[lk+0][lrow] = av.x; As[lk+1][lrow] = av.y; As[lk+2][lrow] = av.z; As[lk+3][lrow] = av.w;
        Gs[lk+0][lrow] = gv.x; Gs[lk+1][lrow] = gv.y; Gs[lk+2][lrow] = gv.z; Gs[lk+3][lrow] = gv.w;
        Us[lk+0][lrow] = uv.x; Us[lk+1][lrow] = uv.y; Us[lk+2][lrow] = uv.z; Us[lk+3][lrow] = uv.w;
        __syncthreads();
        #pragma unroll
        for (int kk = 0; kk < BK; kk++) {
            float a[4], g[4], u[4];
            *(float4*)a = *(const float4*)&As[kk][ty * 4];
            *(float4*)g = *(const float4*)&Gs[kk][tx * 4];
            *(float4*)u = *(const float4*)&Us[kk][tx * 4];
            #pragma unroll
            for (int i = 0; i < 4; i++)
                #pragma unroll
                for (int j = 0; j < 4; j++) {
                    accG[i][j] = fmaf(a[i], g[j], accG[i][j]);
                    accU[i][j] = fmaf(a[i], u[j], accU[i][j]);
                }
        }
        __syncthreads();
    }

    #pragma unroll
    for (int i = 0; i < 4; i++) {
        int rr = m0 + ty * 4 + i;
        float* hb = g_hidden_sh + (size_t)rr * SH_I + n0 + tx * 4;
        #pragma unroll
        for (int j = 0; j < 4; j++) {
            float gval = accG[i][j];
            float sil  = gval / (1.f + expf(-gval));
            hb[j] = sil * accU[i][j];
        }
    }
}

// out[t][h] = hidden_sh[t] . shared_down_w[h]   (plain store, runs BEFORE routed adds)
__global__ __launch_bounds__(NTHREADS)
void shared_down_kernel(const float* __restrict__ DW, float* __restrict__ out) {
    int m0 = blockIdx.y * BM;
    int n0 = blockIdx.x * BN;   // over H

    __shared__ float As[BK][BM + 4];
    __shared__ float Bs[BK][BN + 4];

    int tid  = threadIdx.x;
    int tx   = tid & 15;
    int ty   = tid >> 4;
    int lrow = tid >> 2;
    int lk   = (tid & 3) * 4;

    const float* arow = g_hidden_sh + (size_t)(m0 + lrow) * SH_I;
    const float* brow = DW + (size_t)(n0 + lrow) * SH_I;

    float acc[4][4] = {{0}};
    for (int k0 = 0; k0 < SH_I; k0 += BK) {
        float4 av = *(const float4*)(arow + k0 + lk);
        float4 bv = *(const float4*)(brow + k0 + lk);
        As[lk+0][lrow] = av.x; As[lk+1][lrow] = av.y; As[lk+2][lrow] = av.z; As[lk+3][lrow] = av.w;
        Bs[lk+0][lrow] = bv.x; Bs[lk+1][lrow] = bv.y; Bs[lk+2][lrow] = bv.z; Bs[lk+3][lrow] = bv.w;
        __syncthreads();
        #pragma unroll
        for (int kk = 0; kk < BK; kk++) {
            float a[4], b[4];
            *(float4*)a = *(const float4*)&As[kk][ty * 4];
            *(float4*)b = *(const float4*)&Bs[kk][tx * 4];
            #pragma unroll
            for (int i = 0; i < 4; i++)
                #pragma unroll
                for (int j = 0; j < 4; j++)
                    acc[i][j] = fmaf(a[i], b[j], acc[i][j]);
        }
        __syncthreads();
    }

    #pragma unroll
    for (int i = 0; i < 4; i++) {
        int rr = m0 + ty * 4 + i;
        float* op = out + (size_t)rr * H_DIM + n0 + tx * 4;
        #pragma unroll
        for (int j = 0; j < 4; j++)
            op[j] = acc[i][j];
    }
}

// ---------------------------------------------------------------------------
extern "C" void kernel_launch(void* const* d_in, const int* in_sizes, int n_in,
                              void* d_out, int out_size) {
    const float* hs  = (const float*)d_in[0];   // [2,1024,1024]
    const float* rw  = (const float*)d_in[1];   // [32,1024]
    const float* rb  = (const float*)d_in[2];   // [32]
    const float* gw  = (const float*)d_in[3];   // [32,512,1024]
    const float* uw  = (const float*)d_in[4];   // [32,512,1024]
    const float* dw  = (const float*)d_in[5];   // [32,1024,512]
    const float* sgw = (const float*)d_in[6];   // [1024,1024]
    const float* suw = (const float*)d_in[7];   // [1024,1024]
    const float* sdw = (const float*)d_in[8];   // [1024,1024]
    float* out = (float*)d_out;                 // [2,1024,1024]

    zero_counts_kernel<<<1, 32>>>();
    router_kernel<<<T_TOK / 4, 128>>>(hs, rw, rb);

    // shared experts (shared_down WRITES out; must precede routed atomicAdds)
    shared_gateup_kernel<<<dim3(SH_I / BN, T_TOK / BM), NTHREADS>>>(hs, sgw, suw);
    shared_down_kernel  <<<dim3(H_DIM / BN, T_TOK / BM), NTHREADS>>>(sdw, out);

    // routed experts
    expert_gateup_kernel<<<dim3(I_DIM / BN, T_TOK / BM, N_EXP), NTHREADS>>>(hs, gw, uw);
    expert_down_kernel  <<<dim3(H_DIM / BN, T_TOK / BM, N_EXP), NTHREADS>>>(dw, out);
}

// round 3
// speedup vs baseline: 1.6675x; 1.6675x over previous
#include <cuda_runtime.h>
#include <cuda_bf16.h>
#include <math.h>
#include <stdint.h>

// Problem constants
#define T_TOK   2048
#define H_DIM   1024
#define I_DIM   512
#define N_EXP   32
#define TOP_K   4
#define N_GROUP 4
#define GRP_SZ  8
#define SCALE   2.5f
#define SH_I    1024

#define SK 20   // smem row stride in 32-bit words (16 data + 4 pad -> conflict-free frags)

// ---------------- scratch ----------------------------------------------------
__device__ float g_hidden[(size_t)N_EXP * T_TOK * I_DIM];
__device__ float g_hidden_sh[(size_t)T_TOK * SH_I];
__device__ int   g_counts[N_EXP];
__device__ int   g_tok[N_EXP * T_TOK];
__device__ float g_wt[N_EXP * T_TOK];

// ---------------- tf32 helpers ----------------------------------------------
__device__ __forceinline__ uint32_t f2tf(float x) {
    uint32_t r; asm("cvt.rna.tf32.f32 %0, %1;" : "=r"(r) : "f"(x)); return r;
}
__device__ __forceinline__ void mma8(float* c, const uint32_t* a, uint32_t b0, uint32_t b1) {
    asm volatile("mma.sync.aligned.m16n8k8.row.col.f32.tf32.tf32.f32 "
        "{%0,%1,%2,%3}, {%4,%5,%6,%7}, {%8,%9}, {%0,%1,%2,%3};\n"
        : "+f"(c[0]), "+f"(c[1]), "+f"(c[2]), "+f"(c[3])
        : "r"(a[0]), "r"(a[1]), "r"(a[2]), "r"(a[3]), "r"(b0), "r"(b1));
}
__device__ __forceinline__ void sts8(uint32_t* row, int koff, float4 x, float4 y) {
    row[koff+0]=f2tf(x.x); row[koff+1]=f2tf(x.y); row[koff+2]=f2tf(x.z); row[koff+3]=f2tf(x.w);
    row[koff+4]=f2tf(y.x); row[koff+5]=f2tf(y.y); row[koff+6]=f2tf(y.z); row[koff+7]=f2tf(y.w);
}
__device__ __forceinline__ void sts4(uint32_t* row, int koff, float4 x) {
    row[koff+0]=f2tf(x.x); row[koff+1]=f2tf(x.y); row[koff+2]=f2tf(x.z); row[koff+3]=f2tf(x.w);
}

// ---------------------------------------------------------------------------
__global__ void zero_counts_kernel() {
    if (threadIdx.x < N_EXP) g_counts[threadIdx.x] = 0;
}

// One warp per token (validated in R2).
__global__ void router_kernel(const float* __restrict__ hs,
                              const float* __restrict__ rw,
                              const float* __restrict__ rb) {
    int warp = threadIdx.x >> 5;
    int lane = threadIdx.x & 31;
    int t = blockIdx.x * (blockDim.x >> 5) + warp;
    if (t >= T_TOK) return;

    const float* x = hs + (size_t)t * H_DIM;
    const float* w = rw + (size_t)lane * H_DIM;

    float a0 = 0.f, a1 = 0.f, a2 = 0.f, a3 = 0.f;
    #pragma unroll 4
    for (int h = 0; h < H_DIM; h += 4) {
        a0 = fmaf(x[h + 0], w[h + 0], a0);
        a1 = fmaf(x[h + 1], w[h + 1], a1);
        a2 = fmaf(x[h + 2], w[h + 2], a2);
        a3 = fmaf(x[h + 3], w[h + 3], a3);
    }
    float logit = (a0 + a1) + (a2 + a3);
    float score = 1.f / (1.f + expf(-logit));
    float sfc   = score + rb[lane];

    float s[N_EXP], sc[N_EXP];
    #pragma unroll
    for (int e = 0; e < N_EXP; e++) {
        s[e]  = __shfl_sync(0xffffffffu, sfc, e);
        sc[e] = __shfl_sync(0xffffffffu, score, e);
    }

    if (lane == 0) {
        float gsc[N_GROUP];
        #pragma unroll
        for (int g = 0; g < N_GROUP; g++) {
            float m1 = -1e30f, m2 = -1e30f;
            #pragma unroll
            for (int j = 0; j < GRP_SZ; j++) {
                float v = s[g * GRP_SZ + j];
                if (v > m1) { m2 = m1; m1 = v; }
                else if (v > m2) { m2 = v; }
            }
            gsc[g] = m1 + m2;
        }
        int g1 = 0;
        #pragma unroll
        for (int g = 1; g < N_GROUP; g++) if (gsc[g] > gsc[g1]) g1 = g;
        int g2 = -1;
        #pragma unroll
        for (int g = 0; g < N_GROUP; g++) {
            if (g == g1) continue;
            if (g2 < 0 || gsc[g] > gsc[g2]) g2 = g;
        }
        float v[N_EXP];
        #pragma unroll
        for (int e = 0; e < N_EXP; e++) {
            int g = e / GRP_SZ;
            v[e] = (g == g1 || g == g2) ? s[e] : -1e30f;
        }
        int   idx[TOP_K];
        float wsum = 0.f;
        #pragma unroll
        for (int k = 0; k < TOP_K; k++) {
            int b = 0;
            #pragma unroll
            for (int e = 1; e < N_EXP; e++) if (v[e] > v[b]) b = e;
            idx[k] = b;
            v[b] = -2e30f;
            wsum += sc[b];
        }
        float inv = SCALE / (wsum + 1e-20f);
        #pragma unroll
        for (int k = 0; k < TOP_K; k++) {
            int e = idx[k];
            int p = atomicAdd(&g_counts[e], 1);
            g_tok[e * T_TOK + p] = t;
            g_wt [e * T_TOK + p] = sc[e] * inv;
        }
    }
}

// ---------------------------------------------------------------------------
// Routed gate+up, tf32 tensor cores. CTA tile: M=128, N=64 (per matrix), K-step 16.
// 8 warps as 4m x 2n; warp tile 32x32 per matrix.
__global__ __launch_bounds__(256, 1)
void expert_gateup_tc(const float* __restrict__ X,
                      const float* __restrict__ GW,
                      const float* __restrict__ UW) {
    int e   = blockIdx.z;
    int cnt = g_counts[e];
    int m0  = blockIdx.y * 128;
    if (m0 >= cnt) return;
    int n0  = blockIdx.x * 64;

    __shared__ uint32_t As[2][128][SK];
    __shared__ uint32_t Gs[2][64][SK];
    __shared__ uint32_t Us[2][64][SK];

    int tid = threadIdx.x;
    int lane = tid & 31, wid = tid >> 5;
    int gid = lane >> 2, tig = lane & 3;
    int wm = (wid & 3) * 32;
    int wn = (wid >> 2) * 32;

    // loaders
    int ar = tid >> 1;                 // 0..127
    int ak = (tid & 1) * 8;            // 0 / 8
    int arow = m0 + ar; if (arow >= cnt) arow = cnt - 1;
    const float* aptr = X + (size_t)g_tok[e * T_TOK + arow] * H_DIM + ak;

    int br = tid >> 2;                 // 0..63
    int bk = (tid & 3) * 4;            // 0,4,8,12
    const float* gptr = GW + ((size_t)e * I_DIM + n0 + br) * H_DIM + bk;
    const float* uptr = UW + ((size_t)e * I_DIM + n0 + br) * H_DIM + bk;

    // prologue fill buffer 0
    {
        float4 va0 = *(const float4*)(aptr + 0);
        float4 va1 = *(const float4*)(aptr + 4);
        sts8(As[0][ar], ak, va0, va1);
        sts4(Gs[0][br], bk, *(const float4*)gptr);
        sts4(Us[0][br], bk, *(const float4*)uptr);
    }
    __syncthreads();

    float accG[2][4][4] = {{{0}}};
    float accU[2][4][4] = {{{0}}};

    const int NIT = H_DIM / 16;   // 64
    for (int it = 0; it < NIT; it++) {
        int b = it & 1;
        bool more = (it + 1 < NIT);
        float4 va0, va1, vg, vu;
        if (more) {
            int kb = (it + 1) * 16;
            va0 = *(const float4*)(aptr + kb);
            va1 = *(const float4*)(aptr + kb + 4);
            vg  = *(const float4*)(gptr + kb);
            vu  = *(const float4*)(uptr + kb);
        }
        #pragma unroll
        for (int ks = 0; ks < 2; ks++) {
            int k = ks * 8 + tig;
            uint32_t a[2][4];
            #pragma unroll
            for (int mt = 0; mt < 2; mt++) {
                int r0 = wm + mt * 16 + gid;
                a[mt][0] = As[b][r0    ][k];
                a[mt][1] = As[b][r0 + 8][k];
                a[mt][2] = As[b][r0    ][k + 4];
                a[mt][3] = As[b][r0 + 8][k + 4];
            }
            #pragma unroll
            for (int nt = 0; nt < 4; nt++) {
                int c = wn + nt * 8 + gid;
                uint32_t bg0 = Gs[b][c][k], bg1 = Gs[b][c][k + 4];
                uint32_t bu0 = Us[b][c][k], bu1 = Us[b][c][k + 4];
                mma8(accG[0][nt], a[0], bg0, bg1);
                mma8(accG[1][nt], a[1], bg0, bg1);
                mma8(accU[0][nt], a[0], bu0, bu1);
                mma8(accU[1][nt], a[1], bu0, bu1);
            }
        }
        if (more) {
            int nb = (it + 1) & 1;
            sts8(As[nb][ar], ak, va0, va1);
            sts4(Gs[nb][br], bk, vg);
            sts4(Us[nb][br], bk, vu);
        }
        __syncthreads();
    }

    float* hbase = g_hidden + (size_t)e * T_TOK * I_DIM;
    #pragma unroll
    for (int mt = 0; mt < 2; mt++) {
        #pragma unroll
        for (int half = 0; half < 2; half++) {
            int r = m0 + wm + mt * 16 + gid + half * 8;
            if (r >= cnt) continue;
            #pragma unroll
            for (int nt = 0; nt < 4; nt++) {
                int cb = n0 + wn + nt * 8 + 2 * tig;
                #pragma unroll
                for (int j = 0; j < 2; j++) {
                    float g = accG[mt][nt][half * 2 + j];
                    float u = accU[mt][nt][half * 2 + j];
                    float s = g / (1.f + expf(-g));
                    hbase[(size_t)r * I_DIM + cb + j] = s * u;
                }
            }
        }
    }
}

// Routed down, tf32. CTA tile M=128, N=128, K=I_DIM. Warp tile 32x64.
__global__ __launch_bounds__(256, 1)
void expert_down_tc(const float* __restrict__ DW, float* __restrict__ out) {
    int e   = blockIdx.z;
    int cnt = g_counts[e];
    int m0  = blockIdx.y * 128;
    if (m0 >= cnt) return;
    int n0  = blockIdx.x * 128;

    __shared__ uint32_t As[2][128][SK];
    __shared__ uint32_t Bs[2][128][SK];

    int tid = threadIdx.x;
    int lane = tid & 31, wid = tid >> 5;
    int gid = lane >> 2, tig = lane & 3;
    int wm = (wid & 3) * 32;
    int wn = (wid >> 2) * 64;

    int ar = tid >> 1;
    int ak = (tid & 1) * 8;
    int arow = m0 + ar; if (arow >= cnt) arow = cnt - 1;
    const float* aptr = g_hidden + ((size_t)e * T_TOK + arow) * I_DIM + ak;
    const float* bptr = DW + ((size_t)e * H_DIM + n0 + ar) * I_DIM + ak;

    {
        float4 va0 = *(const float4*)(aptr + 0);
        float4 va1 = *(const float4*)(aptr + 4);
        float4 vb0 = *(const float4*)(bptr + 0);
        float4 vb1 = *(const float4*)(bptr + 4);
        sts8(As[0][ar], ak, va0, va1);
        sts8(Bs[0][ar], ak, vb0, vb1);
    }
    __syncthreads();

    float acc[2][8][4] = {{{0}}};

    const int NIT = I_DIM / 16;   // 32
    for (int it = 0; it < NIT; it++) {
        int b = it & 1;
        bool more = (it + 1 < NIT);
        float4 va0, va1, vb0, vb1;
        if (more) {
            int kb = (it + 1) * 16;
            va0 = *(const float4*)(aptr + kb);
            va1 = *(const float4*)(aptr + kb + 4);
            vb0 = *(const float4*)(bptr + kb);
            vb1 = *(const float4*)(bptr + kb + 4);
        }
        #pragma unroll
        for (int ks = 0; ks < 2; ks++) {
            int k = ks * 8 + tig;
            uint32_t a[2][4];
            #pragma unroll
            for (int mt = 0; mt < 2; mt++) {
                int r0 = wm + mt * 16 + gid;
                a[mt][0] = As[b][r0    ][k];
                a[mt][1] = As[b][r0 + 8][k];
                a[mt][2] = As[b][r0    ][k + 4];
                a[mt][3] = As[b][r0 + 8][k + 4];
            }
            #pragma unroll
            for (int nt = 0; nt < 8; nt++) {
                int c = wn + nt * 8 + gid;
                uint32_t b0 = Bs[b][c][k], b1 = Bs[b][c][k + 4];
                mma8(acc[0][nt], a[0], b0, b1);
                mma8(acc[1][nt], a[1], b0, b1);
            }
        }
        if (more) {
            int nb = (it + 1) & 1;
            sts8(As[nb][ar], ak, va0, va1);
            sts8(Bs[nb][ar], ak, vb0, vb1);
        }
        __syncthreads();
    }

    #pragma unroll
    for (int mt = 0; mt < 2; mt++) {
        #pragma unroll
        for (int half = 0; half < 2; half++) {
            int r = m0 + wm + mt * 16 + gid + half * 8;
            if (r >= cnt) continue;
            int   tok = g_tok[e * T_TOK + r];
            float wt  = g_wt [e * T_TOK + r];
            float* op = out + (size_t)tok * H_DIM;
            #pragma unroll
            for (int nt = 0; nt < 8; nt++) {
                int cb = n0 + wn + nt * 8 + 2 * tig;
                atomicAdd(&op[cb    ], acc[mt][nt][half * 2    ] * wt);
                atomicAdd(&op[cb + 1], acc[mt][nt][half * 2 + 1] * wt);
            }
        }
    }
}

// Shared gate+up (dense, M=T_TOK). Same structure, no gather/clamp.
__global__ __launch_bounds__(256, 1)
void shared_gateup_tc(const float* __restrict__ X,
                      const float* __restrict__ GW,
                      const float* __restrict__ UW) {
    int m0 = blockIdx.y * 128;
    int n0 = blockIdx.x * 64;

    __shared__ uint32_t As[2][128][SK];
    __shared__ uint32_t Gs[2][64][SK];
    __shared__ uint32_t Us[2][64][SK];

    int tid = threadIdx.x;
    int lane = tid & 31, wid = tid >> 5;
    int gid = lane >> 2, tig = lane & 3;
    int wm = (wid & 3) * 32;
    int wn = (wid >> 2) * 32;

    int ar = tid >> 1;
    int ak = (tid & 1) * 8;
    const float* aptr = X + (size_t)(m0 + ar) * H_DIM + ak;

    int br = tid >> 2;
    int bk = (tid & 3) * 4;
    const float* gptr = GW + (size_t)(n0 + br) * H_DIM + bk;
    const float* uptr = UW + (size_t)(n0 + br) * H_DIM + bk;

    {
        float4 va0 = *(const float4*)(aptr + 0);
        float4 va1 = *(const float4*)(aptr + 4);
        sts8(As[0][ar], ak, va0, va1);
        sts4(Gs[0][br], bk, *(const float4*)gptr);
        sts4(Us[0][br], bk, *(const float4*)uptr);
    }
    __syncthreads();

    float accG[2][4][4] = {{{0}}};
    float accU[2][4][4] = {{{0}}};

    const int NIT = H_DIM / 16;
    for (int it = 0; it < NIT; it++) {
        int b = it & 1;
        bool more = (it + 1 < NIT);
        float4 va0, va1, vg, vu;
        if (more) {
            int kb = (it + 1) * 16;
            va0 = *(const float4*)(aptr + kb);
            va1 = *(const float4*)(aptr + kb + 4);
            vg  = *(const float4*)(gptr + kb);
            vu  = *(const float4*)(uptr + kb);
        }
        #pragma unroll
        for (int ks = 0; ks < 2; ks++) {
            int k = ks * 8 + tig;
            uint32_t a[2][4];
            #pragma unroll
            for (int mt = 0; mt < 2; mt++) {
                int r0 = wm + mt * 16 + gid;
                a[mt][0] = As[b][r0    ][k];
                a[mt][1] = As[b][r0 + 8][k];
                a[mt][2] = As[b][r0    ][k + 4];
                a[mt][3] = As[b][r0 + 8][k + 4];
            }
            #pragma unroll
            for (int nt = 0; nt < 4; nt++) {
                int c = wn + nt * 8 + gid;
                uint32_t bg0 = Gs[b][c][k], bg1 = Gs[b][c][k + 4];
                uint32_t bu0 = Us[b][c][k], bu1 = Us[b][c][k + 4];
                mma8(accG[0][nt], a[0], bg0, bg1);
                mma8(accG[1][nt], a[1], bg0, bg1);
                mma8(accU[0][nt], a[0], bu0, bu1);
                mma8(accU[1][nt], a[1], bu0, bu1);
            }
        }
        if (more) {
            int nb = (it + 1) & 1;
            sts8(As[nb][ar], ak, va0, va1);
            sts4(Gs[nb][br], bk, vg);
            sts4(Us[nb][br], bk, vu);
        }
        __syncthreads();
    }

    #pragma unroll
    for (int mt = 0; mt < 2; mt++) {
        #pragma unroll
        for (int half = 0; half < 2; half++) {
            int r = m0 + wm + mt * 16 + gid + half * 8;
            #pragma unroll
            for (int nt = 0; nt < 4; nt++) {
                int cb = n0 + wn + nt * 8 + 2 * tig;
                #pragma unroll
                for (int j = 0; j < 2; j++) {
                    float g = accG[mt][nt][half * 2 + j];
                    float u = accU[mt][nt][half * 2 + j];
                    float s = g / (1.f + expf(-g));
                    g_hidden_sh[(size_t)r * SH_I + cb + j] = s * u;
                }
            }
        }
    }
}

// Shared down (dense): out = hidden_sh @ sdw^T. Plain stores (runs before atomics).
__global__ __launch_bounds__(256, 1)
void shared_down_tc(const float* __restrict__ DW, float* __restrict__ out) {
    int m0 = blockIdx.y * 128;
    int n0 = blockIdx.x * 128;

    __shared__ uint32_t As[2][128][SK];
    __shared__ uint32_t Bs[2][128][SK];

    int tid = threadIdx.x;
    int lane = tid & 31, wid = tid >> 5;
    int gid = lane >> 2, tig = lane & 3;
    int wm = (wid & 3) * 32;
    int wn = (wid >> 2) * 64;

    int ar = tid >> 1;
    int ak = (tid & 1) * 8;
    const float* aptr = g_hidden_sh + (size_t)(m0 + ar) * SH_I + ak;
    const float* bptr = DW + (size_t)(n0 + ar) * SH_I + ak;

    {
        float4 va0 = *(const float4*)(aptr + 0);
        float4 va1 = *(const float4*)(aptr + 4);
        float4 vb0 = *(const float4*)(bptr + 0);
        float4 vb1 = *(const float4*)(bptr + 4);
        sts8(As[0][ar], ak, va0, va1);
        sts8(Bs[0][ar], ak, vb0, vb1);
    }
    __syncthreads();

    float acc[2][8][4] = {{{0}}};

    const int NIT = SH_I / 16;   // 64
    for (int it = 0; it < NIT; it++) {
        int b = it & 1;
        bool more = (it + 1 < NIT);
        float4 va0, va1, vb0, vb1;
        if (more) {
            int kb = (it + 1) * 16;
            va0 = *(const float4*)(aptr + kb);
            va1 = *(const float4*)(aptr + kb + 4);
            vb0 = *(const float4*)(bptr + kb);
            vb1 = *(const float4*)(bptr + kb + 4);
        }
        #pragma unroll
        for (int ks = 0; ks < 2; ks++) {
            int k = ks * 8 + tig;
            uint32_t a[2][4];
            #pragma unroll
            for (int mt = 0; mt < 2; mt++) {
                int r0 = wm + mt * 16 + gid;
                a[mt][0] = As[b][r0    ][k];
                a[mt][1] = As[b][r0 + 8][k];
                a[mt][2] = As[b][r0    ][k + 4];
                a[mt][3] = As[b][r0 + 8][k + 4];
            }
            #pragma unroll
            for (int nt = 0; nt < 8; nt++) {
                int c = wn + nt * 8 + gid;
                uint32_t b0 = Bs[b][c][k], b1 = Bs[b][c][k + 4];
                mma8(acc[0][nt], a[0], b0, b1);
                mma8(acc[1][nt], a[1], b0, b1);
            }
        }
        if (more) {
            int nb = (it + 1) & 1;
            sts8(As[nb][ar], ak, va0, va1);
            sts8(Bs[nb][ar], ak, vb0, vb1);
        }
        __syncthreads();
    }

    #pragma unroll
    for (int mt = 0; mt < 2; mt++) {
        #pragma unroll
        for (int half = 0; half < 2; half++) {
            int r = m0 + wm + mt * 16 + gid + half * 8;
            float* op = out + (size_t)r * H_DIM;
            #pragma unroll
            for (int nt = 0; nt < 8; nt++) {
                int cb = n0 + wn + nt * 8 + 2 * tig;
                op[cb    ] = acc[mt][nt][half * 2    ];
                op[cb + 1] = acc[mt][nt][half * 2 + 1];
            }
        }
    }
}

// ---------------------------------------------------------------------------
extern "C" void kernel_launch(void* const* d_in, const int* in_sizes, int n_in,
                              void* d_out, int out_size) {
    const float* hs  = (const float*)d_in[0];
    const float* rw  = (const float*)d_in[1];
    const float* rb  = (const float*)d_in[2];
    const float* gw  = (const float*)d_in[3];
    const float* uw  = (const float*)d_in[4];
    const float* dw  = (const float*)d_in[5];
    const float* sgw = (const float*)d_in[6];
    const float* suw = (const float*)d_in[7];
    const float* sdw = (const float*)d_in[8];
    float* out = (float*)d_out;

    zero_counts_kernel<<<1, 32>>>();
    router_kernel<<<T_TOK / 4, 128>>>(hs, rw, rb);

    // shared experts (shared_down WRITES out; must precede routed atomicAdds)
    shared_gateup_tc<<<dim3(SH_I / 64, T_TOK / 128), 256>>>(hs, sgw, suw);
    shared_down_tc  <<<dim3(H_DIM / 128, T_TOK / 128), 256>>>(sdw, out);

    // routed experts
    expert_gateup_tc<<<dim3(I_DIM / 64, T_TOK / 128, N_EXP), 256>>>(hs, gw, uw);
    expert_down_tc  <<<dim3(H_DIM / 128, T_TOK / 128, N_EXP), 256>>>(dw, out);
}

// round 4
// speedup vs baseline: 1.7859x; 1.0710x over previous
#include <cuda_runtime.h>
#include <cuda_bf16.h>
#include <math.h>
#include <stdint.h>

#define T_TOK   2048
#define H_DIM   1024
#define I_DIM   512
#define N_EXP   32
#define TOP_K   4
#define N_GROUP 4
#define GRP_SZ  8
#define SCALE   2.5f
#define SH_I    1024

// ---------------- scratch ----------------------------------------------------
__device__ float g_hidden[(size_t)N_EXP * T_TOK * I_DIM];
__device__ float g_hidden_sh[(size_t)T_TOK * SH_I];
__device__ int   g_counts[N_EXP];
__device__ int   g_tok[N_EXP * T_TOK];
__device__ float g_wt[N_EXP * T_TOK];

// ---------------- tf32 helpers ----------------------------------------------
__device__ __forceinline__ uint32_t f2tf(float x) {
    uint32_t r; asm("cvt.rna.tf32.f32 %0, %1;" : "=r"(r) : "f"(x)); return r;
}
__device__ __forceinline__ void mma8(float* c, const uint32_t* a, uint32_t b0, uint32_t b1) {
    asm volatile("mma.sync.aligned.m16n8k8.row.col.f32.tf32.tf32.f32 "
        "{%0,%1,%2,%3}, {%4,%5,%6,%7}, {%8,%9}, {%0,%1,%2,%3};\n"
        : "+f"(c[0]), "+f"(c[1]), "+f"(c[2]), "+f"(c[3])
        : "r"(a[0]), "r"(a[1]), "r"(a[2]), "r"(a[3]), "r"(b0), "r"(b1));
}

// Fragment-layout STS helpers.
// A layout (128 rows x 16 k): word index = t*256 + ks8*128 + g*16 + klsw*4 + (h + 2*k4)
//   where r = t*16 + h*8 + g, k = ks8*8 + k4*4 + kl, klsw = kl ^ (g&3) ^ (ks8<<1).
// Reader: LDS.128 at (t, ks8, g=gid, klsw(tig)) -> {a0,a1,a2,a3} for m16n8k8.
__device__ __forceinline__ void stsA_frag(uint32_t* buf, int lr, int lks,
                                          float4 v0, float4 v1) {
    int lt = lr >> 4, lg = lr & 7, lh = (lr >> 3) & 1;
    int base = lt * 256 + lks * 128 + lg * 16;
    int x = (lg & 3) ^ (lks << 1);
    float f[8] = {v0.x, v0.y, v0.z, v0.w, v1.x, v1.y, v1.z, v1.w};
    #pragma unroll
    for (int i = 0; i < 8; i++) {
        int kl = i & 3, k4 = i >> 2;
        buf[base + ((kl ^ x) << 2) + lh + (k4 << 1)] = f2tf(f[i]);
    }
}
// B layout (cols c x 16 k): word index = c*16 + klsw*4 + (k4 + 2*ks8)
//   klsw = kl ^ (c&3) ^ (((c>>3)&1)<<1).
// Reader: LDS.128 at (c, klsw(tig)) -> {b0_ks0, b1_ks0, b0_ks1, b1_ks1}.
__device__ __forceinline__ void stsB_frag8(uint32_t* buf, int c, int lks,
                                           float4 v0, float4 v1) {
    int base = c * 16;
    int x = (c & 3) ^ (((c >> 3) & 1) << 1);
    float f[8] = {v0.x, v0.y, v0.z, v0.w, v1.x, v1.y, v1.z, v1.w};
    #pragma unroll
    for (int i = 0; i < 8; i++) {
        int kl = i & 3, k4 = i >> 2;
        buf[base + ((kl ^ x) << 2) + k4 + (lks << 1)] = f2tf(f[i]);
    }
}
// B variant: thread holds 4 consecutive k at quarter q (q = k>>2 = elem index).
__device__ __forceinline__ void stsB_frag4(uint32_t* buf, int c, int q, float4 v) {
    int base = c * 16;
    int x = (c & 3) ^ (((c >> 3) & 1) << 1);
    float f[4] = {v.x, v.y, v.z, v.w};
    #pragma unroll
    for (int j = 0; j < 4; j++)
        buf[base + ((j ^ x) << 2) + q] = f2tf(f[j]);
}

__device__ __forceinline__ uint4 ldA_frag(const uint32_t* buf, int t, int ks, int gid, int tig) {
    int x = (gid & 3) ^ (ks << 1);
    return *(const uint4*)&buf[t * 256 + ks * 128 + gid * 16 + ((tig ^ x) << 2)];
}
__device__ __forceinline__ uint4 ldB_frag(const uint32_t* buf, int c, int tig) {
    int x = (c & 3) ^ (((c >> 3) & 1) << 1);
    return *(const uint4*)&buf[c * 16 + ((tig ^ x) << 2)];
}

// ---------------------------------------------------------------------------
__global__ void zero_counts_kernel() {
    if (threadIdx.x < N_EXP) g_counts[threadIdx.x] = 0;
}

__global__ void router_kernel(const float* __restrict__ hs,
                              const float* __restrict__ rw,
                              const float* __restrict__ rb) {
    int warp = threadIdx.x >> 5;
    int lane = threadIdx.x & 31;
    int t = blockIdx.x * (blockDim.x >> 5) + warp;
    if (t >= T_TOK) return;

    const float* x = hs + (size_t)t * H_DIM;
    const float* w = rw + (size_t)lane * H_DIM;

    float a0 = 0.f, a1 = 0.f, a2 = 0.f, a3 = 0.f;
    #pragma unroll 4
    for (int h = 0; h < H_DIM; h += 4) {
        a0 = fmaf(x[h + 0], w[h + 0], a0);
        a1 = fmaf(x[h + 1], w[h + 1], a1);
        a2 = fmaf(x[h + 2], w[h + 2], a2);
        a3 = fmaf(x[h + 3], w[h + 3], a3);
    }
    float logit = (a0 + a1) + (a2 + a3);
    float score = 1.f / (1.f + expf(-logit));
    float sfc   = score + rb[lane];

    float s[N_EXP], sc[N_EXP];
    #pragma unroll
    for (int e = 0; e < N_EXP; e++) {
        s[e]  = __shfl_sync(0xffffffffu, sfc, e);
        sc[e] = __shfl_sync(0xffffffffu, score, e);
    }

    if (lane == 0) {
        float gsc[N_GROUP];
        #pragma unroll
        for (int g = 0; g < N_GROUP; g++) {
            float m1 = -1e30f, m2 = -1e30f;
            #pragma unroll
            for (int j = 0; j < GRP_SZ; j++) {
                float v = s[g * GRP_SZ + j];
                if (v > m1) { m2 = m1; m1 = v; }
                else if (v > m2) { m2 = v; }
            }
            gsc[g] = m1 + m2;
        }
        int g1 = 0;
        #pragma unroll
        for (int g = 1; g < N_GROUP; g++) if (gsc[g] > gsc[g1]) g1 = g;
        int g2 = -1;
        #pragma unroll
        for (int g = 0; g < N_GROUP; g++) {
            if (g == g1) continue;
            if (g2 < 0 || gsc[g] > gsc[g2]) g2 = g;
        }
        float v[N_EXP];
        #pragma unroll
        for (int e = 0; e < N_EXP; e++) {
            int g = e / GRP_SZ;
            v[e] = (g == g1 || g == g2) ? s[e] : -1e30f;
        }
        int   idx[TOP_K];
        float wsum = 0.f;
        #pragma unroll
        for (int k = 0; k < TOP_K; k++) {
            int b = 0;
            #pragma unroll
            for (int e = 1; e < N_EXP; e++) if (v[e] > v[b]) b = e;
            idx[k] = b;
            v[b] = -2e30f;
            wsum += sc[b];
        }
        float inv = SCALE / (wsum + 1e-20f);
        #pragma unroll
        for (int k = 0; k < TOP_K; k++) {
            int e = idx[k];
            int p = atomicAdd(&g_counts[e], 1);
            g_tok[e * T_TOK + p] = t;
            g_wt [e * T_TOK + p] = sc[e] * inv;
        }
    }
}

// ---------------------------------------------------------------------------
// Gate+up core: CTA tile M=128, N=64 per matrix; warps 4m x 2n; warp tile 32x32/matrix.
template <bool ROUTED>
__device__ __forceinline__ void gateup_body(
    const float* __restrict__ X, const float* __restrict__ GW,
    const float* __restrict__ UW, float* __restrict__ H_out,
    int e, int cnt, int m0, int n0, int ldh)
{
    __shared__ uint32_t As[2][2048];
    __shared__ uint32_t Gs[2][1024];
    __shared__ uint32_t Us[2][1024];

    int tid = threadIdx.x;
    int lane = tid & 31, wid = tid >> 5;
    int gid = lane >> 2, tig = lane & 3;
    int wm = (wid & 3) * 32;
    int wn = (wid >> 2) * 32;

    // A loader: row = tid>>1, k-half = tid&1
    int lr = tid >> 1;
    int lks = tid & 1;
    int arow = m0 + lr;
    if (ROUTED) { if (arow >= cnt) arow = cnt - 1; }
    const float* aptr;
    if (ROUTED) aptr = X + (size_t)g_tok[e * T_TOK + arow] * H_DIM + lks * 8;
    else        aptr = X + (size_t)arow * H_DIM + lks * 8;

    // G/U loader: row = tid>>2, quarter q = tid&3
    int br = tid >> 2;
    int bq = tid & 3;
    const float* gptr = GW + (size_t)(n0 + br) * H_DIM + bq * 4;
    const float* uptr = UW + (size_t)(n0 + br) * H_DIM + bq * 4;

    {
        float4 va0 = *(const float4*)(aptr + 0);
        float4 va1 = *(const float4*)(aptr + 4);
        stsA_frag(As[0], lr, lks, va0, va1);
        stsB_frag4(Gs[0], br, bq, *(const float4*)gptr);
        stsB_frag4(Us[0], br, bq, *(const float4*)uptr);
    }
    __syncthreads();

    float accG[2][4][4] = {{{0}}};
    float accU[2][4][4] = {{{0}}};

    const int NIT = H_DIM / 16;
    for (int it = 0; it < NIT; it++) {
        int b = it & 1;
        bool more = (it + 1 < NIT);
        float4 va0, va1, vg, vu;
        if (more) {
            int kb = (it + 1) * 16;
            va0 = *(const float4*)(aptr + kb);
            va1 = *(const float4*)(aptr + kb + 4);
            vg  = *(const float4*)(gptr + kb);
            vu  = *(const float4*)(uptr + kb);
        }
        uint32_t a[2][2][4];   // [mt][ks][4]
        #pragma unroll
        for (int mt = 0; mt < 2; mt++) {
            int t = (wid & 3) * 2 + mt;
            #pragma unroll
            for (int ks = 0; ks < 2; ks++) {
                uint4 av = ldA_frag(As[b], t, ks, gid, tig);
                a[mt][ks][0] = av.x; a[mt][ks][1] = av.y;
                a[mt][ks][2] = av.z; a[mt][ks][3] = av.w;
            }
        }
        #pragma unroll
        for (int nt = 0; nt < 4; nt++) {
            int c = wn + nt * 8 + gid;
            uint4 gv = ldB_frag(Gs[b], c, tig);
            uint4 uv = ldB_frag(Us[b], c, tig);
            mma8(accG[0][nt], a[0][0], gv.x, gv.y);
            mma8(accG[1][nt], a[1][0], gv.x, gv.y);
            mma8(accG[0][nt], a[0][1], gv.z, gv.w);
            mma8(accG[1][nt], a[1][1], gv.z, gv.w);
            mma8(accU[0][nt], a[0][0], uv.x, uv.y);
            mma8(accU[1][nt], a[1][0], uv.x, uv.y);
            mma8(accU[0][nt], a[0][1], uv.z, uv.w);
            mma8(accU[1][nt], a[1][1], uv.z, uv.w);
        }
        if (more) {
            int nb = (it + 1) & 1;
            stsA_frag(As[nb], lr, lks, va0, va1);
            stsB_frag4(Gs[nb], br, bq, vg);
            stsB_frag4(Us[nb], br, bq, vu);
        }
        __syncthreads();
    }

    #pragma unroll
    for (int mt = 0; mt < 2; mt++) {
        #pragma unroll
        for (int half = 0; half < 2; half++) {
            int r = m0 + wm + mt * 16 + gid + half * 8;
            if (ROUTED && r >= cnt) continue;
            #pragma unroll
            for (int nt = 0; nt < 4; nt++) {
                int cb = n0 + wn + nt * 8 + 2 * tig;
                #pragma unroll
                for (int j = 0; j < 2; j++) {
                    float g = accG[mt][nt][half * 2 + j];
                    float u = accU[mt][nt][half * 2 + j];
                    float s = g / (1.f + expf(-g));
                    H_out[(size_t)r * ldh + cb + j] = s * u;
                }
            }
        }
    }
}

__global__ __launch_bounds__(256, 2)
void expert_gateup_tc(const float* __restrict__ X,
                      const float* __restrict__ GW,
                      const float* __restrict__ UW) {
    int e   = blockIdx.z;
    int cnt = g_counts[e];
    int m0  = blockIdx.y * 128;
    if (m0 >= cnt) return;
    int n0  = blockIdx.x * 64;
    gateup_body<true>(X, GW + (size_t)e * I_DIM * H_DIM, UW + (size_t)e * I_DIM * H_DIM,
                      g_hidden + (size_t)e * T_TOK * I_DIM, e, cnt, m0, n0, I_DIM);
}

__global__ __launch_bounds__(256, 2)
void shared_gateup_tc(const float* __restrict__ X,
                      const float* __restrict__ GW,
                      const float* __restrict__ UW) {
    int m0 = blockIdx.y * 128;
    int n0 = blockIdx.x * 64;
    gateup_body<false>(X, GW, UW, g_hidden_sh, 0, T_TOK, m0, n0, SH_I);
}

// ---------------------------------------------------------------------------
// Down core: CTA tile M=128, N=128; warps 4m x 2n; warp tile 32x64. K = KDIM.
template <int KDIM, bool ROUTED>
__device__ __forceinline__ void down_body(
    const float* __restrict__ Ain, const float* __restrict__ DW,
    float* __restrict__ out, int e, int cnt, int m0, int n0)
{
    __shared__ uint32_t As[2][2048];
    __shared__ uint32_t Bs[2][2048];

    int tid = threadIdx.x;
    int lane = tid & 31, wid = tid >> 5;
    int gid = lane >> 2, tig = lane & 3;
    int wm = (wid & 3) * 32;
    int wn = (wid >> 2) * 64;

    int lr = tid >> 1;
    int lks = tid & 1;
    int arow = m0 + lr;
    if (ROUTED) { if (arow >= cnt) arow = cnt - 1; }
    const float* aptr = Ain + (size_t)arow * KDIM + lks * 8;
    const float* bptr = DW + (size_t)(n0 + lr) * KDIM + lks * 8;

    {
        float4 va0 = *(const float4*)(aptr + 0);
        float4 va1 = *(const float4*)(aptr + 4);
        float4 vb0 = *(const float4*)(bptr + 0);
        float4 vb1 = *(const float4*)(bptr + 4);
        stsA_frag(As[0], lr, lks, va0, va1);
        stsB_frag8(Bs[0], lr, lks, vb0, vb1);
    }
    __syncthreads();

    float acc[2][8][4] = {{{0}}};

    const int NIT = KDIM / 16;
    for (int it = 0; it < NIT; it++) {
        int b = it & 1;
        bool more = (it + 1 < NIT);
        float4 va0, va1, vb0, vb1;
        if (more) {
            int kb = (it + 1) * 16;
            va0 = *(const float4*)(aptr + kb);
            va1 = *(const float4*)(aptr + kb + 4);
            vb0 = *(const float4*)(bptr + kb);
            vb1 = *(const float4*)(bptr + kb + 4);
        }
        uint32_t a[2][2][4];
        #pragma unroll
        for (int mt = 0; mt < 2; mt++) {
            int t = (wid & 3) * 2 + mt;
            #pragma unroll
            for (int ks = 0; ks < 2; ks++) {
                uint4 av = ldA_frag(As[b], t, ks, gid, tig);
                a[mt][ks][0] = av.x; a[mt][ks][1] = av.y;
                a[mt][ks][2] = av.z; a[mt][ks][3] = av.w;
            }
        }
        #pragma unroll
        for (int nt = 0; nt < 8; nt++) {
            int c = wn + nt * 8 + gid;
            uint4 bv = ldB_frag(Bs[b], c, tig);
            mma8(acc[0][nt], a[0][0], bv.x, bv.y);
            mma8(acc[1][nt], a[1][0], bv.x, bv.y);
            mma8(acc[0][nt], a[0][1], bv.z, bv.w);
            mma8(acc[1][nt], a[1][1], bv.z, bv.w);
        }
        if (more) {
            int nb = (it + 1) & 1;
            stsA_frag(As[nb], lr, lks, va0, va1);
            stsB_frag8(Bs[nb], lr, lks, vb0, vb1);
        }
        __syncthreads();
    }

    #pragma unroll
    for (int mt = 0; mt < 2; mt++) {
        #pragma unroll
        for (int half = 0; half < 2; half++) {
            int r = m0 + wm + mt * 16 + gid + half * 8;
            if (ROUTED) {
                if (r >= cnt) continue;
                int   tok = g_tok[e * T_TOK + r];
                float wt  = g_wt [e * T_TOK + r];
                float* op = out + (size_t)tok * H_DIM;
                #pragma unroll
                for (int nt = 0; nt < 8; nt++) {
                    int cb = n0 + wn + nt * 8 + 2 * tig;
                    atomicAdd(&op[cb    ], acc[mt][nt][half * 2    ] * wt);
                    atomicAdd(&op[cb + 1], acc[mt][nt][half * 2 + 1] * wt);
                }
            } else {
                float* op = out + (size_t)r * H_DIM;
                #pragma unroll
                for (int nt = 0; nt < 8; nt++) {
                    int cb = n0 + wn + nt * 8 + 2 * tig;
                    op[cb    ] = acc[mt][nt][half * 2    ];
                    op[cb + 1] = acc[mt][nt][half * 2 + 1];
                }
            }
        }
    }
}

__global__ __launch_bounds__(256, 2)
void expert_down_tc(const float* __restrict__ DW, float* __restrict__ out) {
    int e   = blockIdx.z;
    int cnt = g_counts[e];
    int m0  = blockIdx.y * 128;
    if (m0 >= cnt) return;
    int n0  = blockIdx.x * 128;
    down_body<I_DIM, true>(g_hidden + (size_t)e * T_TOK * I_DIM,
                           DW + (size_t)e * H_DIM * I_DIM, out, e, cnt, m0, n0);
}

__global__ __launch_bounds__(256, 2)
void shared_down_tc(const float* __restrict__ DW, float* __restrict__ out) {
    int m0 = blockIdx.y * 128;
    int n0 = blockIdx.x * 128;
    down_body<SH_I, false>(g_hidden_sh, DW, out, 0, T_TOK, m0, n0);
}

// ---------------------------------------------------------------------------
extern "C" void kernel_launch(void* const* d_in, const int* in_sizes, int n_in,
                              void* d_out, int out_size) {
    const float* hs  = (const float*)d_in[0];
    const float* rw  = (const float*)d_in[1];
    const float* rb  = (const float*)d_in[2];
    const float* gw  = (const float*)d_in[3];
    const float* uw  = (const float*)d_in[4];
    const float* dw  = (const float*)d_in[5];
    const float* sgw = (const float*)d_in[6];
    const float* suw = (const float*)d_in[7];
    const float* sdw = (const float*)d_in[8];
    float* out = (float*)d_out;

    zero_counts_kernel<<<1, 32>>>();
    router_kernel<<<T_TOK / 4, 128>>>(hs, rw, rb);

    // shared experts (shared_down WRITES out; must precede routed atomicAdds)
    shared_gateup_tc<<<dim3(SH_I / 64, T_TOK / 128), 256>>>(hs, sgw, suw);
    shared_down_tc  <<<dim3(H_DIM / 128, T_TOK / 128), 256>>>(sdw, out);

    // routed experts
    expert_gateup_tc<<<dim3(I_DIM / 64, T_TOK / 128, N_EXP), 256>>>(hs, gw, uw);
    expert_down_tc  <<<dim3(H_DIM / 128, T_TOK / 128, N_EXP), 256>>>(dw, out);
}

// round 5
// speedup vs baseline: 1.9775x; 1.1073x over previous
#include <cuda_runtime.h>
#include <cuda_bf16.h>
#include <math.h>
#include <stdint.h>

#define T_TOK   2048
#define H_DIM   1024
#define I_DIM   512
#define N_EXP   32
#define TOP_K   4
#define N_GROUP 4
#define GRP_SZ  8
#define SCALE   2.5f
#define SH_I    1024
#define MAXMB   96      // max sum of ceil(cnt_e/128) = 8192/128 + 32

// ---------------- scratch ----------------------------------------------------
__device__ float g_hidden[(size_t)N_EXP * T_TOK * I_DIM];
__device__ float g_hidden_sh[(size_t)T_TOK * SH_I];
__device__ int   g_counts[N_EXP];
__device__ int   g_tok[N_EXP * T_TOK];
__device__ float g_wt[N_EXP * T_TOK];
__device__ int   g_nmb;
__device__ int   g_sched_e[MAXMB];
__device__ int   g_sched_m[MAXMB];

// ---------------- tf32 helpers ----------------------------------------------
__device__ __forceinline__ uint32_t f2tf(float x) {
    uint32_t r; asm("cvt.rna.tf32.f32 %0, %1;" : "=r"(r) : "f"(x)); return r;
}
__device__ __forceinline__ void mma8(float* c, const uint32_t* a, uint32_t b0, uint32_t b1) {
    asm volatile("mma.sync.aligned.m16n8k8.row.col.f32.tf32.tf32.f32 "
        "{%0,%1,%2,%3}, {%4,%5,%6,%7}, {%8,%9}, {%0,%1,%2,%3};\n"
        : "+f"(c[0]), "+f"(c[1]), "+f"(c[2]), "+f"(c[3])
        : "r"(a[0]), "r"(a[1]), "r"(a[2]), "r"(a[3]), "r"(b0), "r"(b1));
}

// Fragment-layout STS/LDS (validated R4).
__device__ __forceinline__ void stsA_frag(uint32_t* buf, int lr, int lks,
                                          float4 v0, float4 v1) {
    int lt = lr >> 4, lg = lr & 7, lh = (lr >> 3) & 1;
    int base = lt * 256 + lks * 128 + lg * 16;
    int x = (lg & 3) ^ (lks << 1);
    float f[8] = {v0.x, v0.y, v0.z, v0.w, v1.x, v1.y, v1.z, v1.w};
    #pragma unroll
    for (int i = 0; i < 8; i++) {
        int kl = i & 3, k4 = i >> 2;
        buf[base + ((kl ^ x) << 2) + lh + (k4 << 1)] = f2tf(f[i]);
    }
}
__device__ __forceinline__ void stsB_frag8(uint32_t* buf, int c, int lks,
                                           float4 v0, float4 v1) {
    int base = c * 16;
    int x = (c & 3) ^ (((c >> 3) & 1) << 1);
    float f[8] = {v0.x, v0.y, v0.z, v0.w, v1.x, v1.y, v1.z, v1.w};
    #pragma unroll
    for (int i = 0; i < 8; i++) {
        int kl = i & 3, k4 = i >> 2;
        buf[base + ((kl ^ x) << 2) + k4 + (lks << 1)] = f2tf(f[i]);
    }
}
__device__ __forceinline__ void stsB_frag4(uint32_t* buf, int c, int q, float4 v) {
    int base = c * 16;
    int x = (c & 3) ^ (((c >> 3) & 1) << 1);
    float f[4] = {v.x, v.y, v.z, v.w};
    #pragma unroll
    for (int j = 0; j < 4; j++)
        buf[base + ((j ^ x) << 2) + q] = f2tf(f[j]);
}
__device__ __forceinline__ uint4 ldA_frag(const uint32_t* buf, int t, int ks, int gid, int tig) {
    int x = (gid & 3) ^ (ks << 1);
    return *(const uint4*)&buf[t * 256 + ks * 128 + gid * 16 + ((tig ^ x) << 2)];
}
__device__ __forceinline__ uint4 ldB_frag(const uint32_t* buf, int c, int tig) {
    int x = (c & 3) ^ (((c >> 3) & 1) << 1);
    return *(const uint4*)&buf[c * 16 + ((tig ^ x) << 2)];
}

// ---------------------------------------------------------------------------
__global__ void zero_counts_kernel() {
    if (threadIdx.x < N_EXP) g_counts[threadIdx.x] = 0;
}

__global__ void zero_out_kernel(float* __restrict__ out) {
    int i = blockIdx.x * blockDim.x + threadIdx.x;
    ((float4*)out)[i] = make_float4(0.f, 0.f, 0.f, 0.f);
}

__global__ void router_kernel(const float* __restrict__ hs,
                              const float* __restrict__ rw,
                              const float* __restrict__ rb) {
    int warp = threadIdx.x >> 5;
    int lane = threadIdx.x & 31;
    int t = blockIdx.x * (blockDim.x >> 5) + warp;
    if (t >= T_TOK) return;

    const float* x = hs + (size_t)t * H_DIM;
    const float* w = rw + (size_t)lane * H_DIM;

    float a0 = 0.f, a1 = 0.f, a2 = 0.f, a3 = 0.f;
    #pragma unroll 4
    for (int h = 0; h < H_DIM; h += 4) {
        a0 = fmaf(x[h + 0], w[h + 0], a0);
        a1 = fmaf(x[h + 1], w[h + 1], a1);
        a2 = fmaf(x[h + 2], w[h + 2], a2);
        a3 = fmaf(x[h + 3], w[h + 3], a3);
    }
    float logit = (a0 + a1) + (a2 + a3);
    float score = 1.f / (1.f + expf(-logit));
    float sfc   = score + rb[lane];

    float s[N_EXP], sc[N_EXP];
    #pragma unroll
    for (int e = 0; e < N_EXP; e++) {
        s[e]  = __shfl_sync(0xffffffffu, sfc, e);
        sc[e] = __shfl_sync(0xffffffffu, score, e);
    }

    if (lane == 0) {
        float gsc[N_GROUP];
        #pragma unroll
        for (int g = 0; g < N_GROUP; g++) {
            float m1 = -1e30f, m2 = -1e30f;
            #pragma unroll
            for (int j = 0; j < GRP_SZ; j++) {
                float v = s[g * GRP_SZ + j];
                if (v > m1) { m2 = m1; m1 = v; }
                else if (v > m2) { m2 = v; }
            }
            gsc[g] = m1 + m2;
        }
        int g1 = 0;
        #pragma unroll
        for (int g = 1; g < N_GROUP; g++) if (gsc[g] > gsc[g1]) g1 = g;
        int g2 = -1;
        #pragma unroll
        for (int g = 0; g < N_GROUP; g++) {
            if (g == g1) continue;
            if (g2 < 0 || gsc[g] > gsc[g2]) g2 = g;
        }
        float v[N_EXP];
        #pragma unroll
        for (int e = 0; e < N_EXP; e++) {
            int g = e / GRP_SZ;
            v[e] = (g == g1 || g == g2) ? s[e] : -1e30f;
        }
        int   idx[TOP_K];
        float wsum = 0.f;
        #pragma unroll
        for (int k = 0; k < TOP_K; k++) {
            int b = 0;
            #pragma unroll
            for (int e = 1; e < N_EXP; e++) if (v[e] > v[b]) b = e;
            idx[k] = b;
            v[b] = -2e30f;
            wsum += sc[b];
        }
        float inv = SCALE / (wsum + 1e-20f);
        #pragma unroll
        for (int k = 0; k < TOP_K; k++) {
            int e = idx[k];
            int p = atomicAdd(&g_counts[e], 1);
            g_tok[e * T_TOK + p] = t;
            g_wt [e * T_TOK + p] = sc[e] * inv;
        }
    }
}

// Build per-expert m-block work list (1 warp).
__global__ void sched_kernel() {
    int lane = threadIdx.x;
    int cnt = (lane < N_EXP) ? g_counts[lane] : 0;
    int nb = (cnt + 127) >> 7;
    int incl = nb;
    #pragma unroll
    for (int off = 1; off < 32; off <<= 1) {
        int v = __shfl_up_sync(0xffffffffu, incl, off);
        if (lane >= off) incl += v;
    }
    int base = incl - nb;
    for (int j = 0; j < nb; j++) {
        g_sched_e[base + j] = lane;
        g_sched_m[base + j] = j * 128;
    }
    if (lane == 31) g_nmb = incl;
}

// ---------------------------------------------------------------------------
// Gate+up core (CTA M=128, N=64 per matrix, 8 warps 4m x 2n).
template <bool ROUTED>
__device__ __forceinline__ void gateup_body(
    const float* __restrict__ X, const float* __restrict__ GW,
    const float* __restrict__ UW, float* __restrict__ H_out,
    int e, int cnt, int m0, int n0, int ldh)
{
    __shared__ uint32_t As[2][2048];
    __shared__ uint32_t Gs[2][1024];
    __shared__ uint32_t Us[2][1024];

    int tid = threadIdx.x;
    int lane = tid & 31, wid = tid >> 5;
    int gid = lane >> 2, tig = lane & 3;
    int wm = (wid & 3) * 32;
    int wn = (wid >> 2) * 32;

    int lr = tid >> 1;
    int lks = tid & 1;
    int arow = m0 + lr;
    if (ROUTED) { if (arow >= cnt) arow = cnt - 1; }
    const float* aptr;
    if (ROUTED) aptr = X + (size_t)g_tok[e * T_TOK + arow] * H_DIM + lks * 8;
    else        aptr = X + (size_t)arow * H_DIM + lks * 8;

    int br = tid >> 2;
    int bq = tid & 3;
    const float* gptr = GW + (size_t)(n0 + br) * H_DIM + bq * 4;
    const float* uptr = UW + (size_t)(n0 + br) * H_DIM + bq * 4;

    {
        float4 va0 = *(const float4*)(aptr + 0);
        float4 va1 = *(const float4*)(aptr + 4);
        stsA_frag(As[0], lr, lks, va0, va1);
        stsB_frag4(Gs[0], br, bq, *(const float4*)gptr);
        stsB_frag4(Us[0], br, bq, *(const float4*)uptr);
    }
    __syncthreads();

    float accG[2][4][4] = {{{0}}};
    float accU[2][4][4] = {{{0}}};

    const int NIT = H_DIM / 16;
    for (int it = 0; it < NIT; it++) {
        int b = it & 1;
        bool more = (it + 1 < NIT);
        float4 va0, va1, vg, vu;
        if (more) {
            int kb = (it + 1) * 16;
            va0 = *(const float4*)(aptr + kb);
            va1 = *(const float4*)(aptr + kb + 4);
            vg  = *(const float4*)(gptr + kb);
            vu  = *(const float4*)(uptr + kb);
        }
        uint32_t a[2][2][4];
        #pragma unroll
        for (int mt = 0; mt < 2; mt++) {
            int t = (wid & 3) * 2 + mt;
            #pragma unroll
            for (int ks = 0; ks < 2; ks++) {
                uint4 av = ldA_frag(As[b], t, ks, gid, tig);
                a[mt][ks][0] = av.x; a[mt][ks][1] = av.y;
                a[mt][ks][2] = av.z; a[mt][ks][3] = av.w;
            }
        }
        #pragma unroll
        for (int nt = 0; nt < 4; nt++) {
            int c = wn + nt * 8 + gid;
            uint4 gv = ldB_frag(Gs[b], c, tig);
            uint4 uv = ldB_frag(Us[b], c, tig);
            mma8(accG[0][nt], a[0][0], gv.x, gv.y);
            mma8(accG[1][nt], a[1][0], gv.x, gv.y);
            mma8(accG[0][nt], a[0][1], gv.z, gv.w);
            mma8(accG[1][nt], a[1][1], gv.z, gv.w);
            mma8(accU[0][nt], a[0][0], uv.x, uv.y);
            mma8(accU[1][nt], a[1][0], uv.x, uv.y);
            mma8(accU[0][nt], a[0][1], uv.z, uv.w);
            mma8(accU[1][nt], a[1][1], uv.z, uv.w);
        }
        if (more) {
            int nb = (it + 1) & 1;
            stsA_frag(As[nb], lr, lks, va0, va1);
            stsB_frag4(Gs[nb], br, bq, vg);
            stsB_frag4(Us[nb], br, bq, vu);
        }
        __syncthreads();
    }

    #pragma unroll
    for (int mt = 0; mt < 2; mt++) {
        #pragma unroll
        for (int half = 0; half < 2; half++) {
            int r = m0 + wm + mt * 16 + gid + half * 8;
            if (ROUTED && r >= cnt) continue;
            #pragma unroll
            for (int nt = 0; nt < 4; nt++) {
                int cb = n0 + wn + nt * 8 + 2 * tig;
                #pragma unroll
                for (int j = 0; j < 2; j++) {
                    float g = accG[mt][nt][half * 2 + j];
                    float u = accU[mt][nt][half * 2 + j];
                    float s = g / (1.f + expf(-g));
                    H_out[(size_t)r * ldh + cb + j] = s * u;
                }
            }
        }
    }
}

// Merged gate+up: blocks [0,256) = shared experts, [256, 256+8*nmb) = routed.
__global__ __launch_bounds__(256, 2)
void gateup_all(const float* __restrict__ X,
                const float* __restrict__ GW, const float* __restrict__ UW,
                const float* __restrict__ SGW, const float* __restrict__ SUW) {
    int bid = blockIdx.x;
    if (bid < 256) {
        int m0 = (bid >> 4) * 128;
        int n0 = (bid & 15) * 64;
        gateup_body<false>(X, SGW, SUW, g_hidden_sh, 0, T_TOK, m0, n0, SH_I);
    } else {
        int rb = bid - 256;
        int mb = rb >> 3;
        if (mb >= g_nmb) return;
        int e   = g_sched_e[mb];
        int m0  = g_sched_m[mb];
        int cnt = g_counts[e];
        int n0  = (rb & 7) * 64;
        gateup_body<true>(X, GW + (size_t)e * I_DIM * H_DIM,
                          UW + (size_t)e * I_DIM * H_DIM,
                          g_hidden + (size_t)e * T_TOK * I_DIM,
                          e, cnt, m0, n0, I_DIM);
    }
}

// ---------------------------------------------------------------------------
// Down core (CTA M=128, N=128, 8 warps 4m x 2n, warp 32x64). Always atomicAdd
// into pre-zeroed out (shared + routed coexist in one grid).
template <int KDIM, bool ROUTED>
__device__ __forceinline__ void down_body(
    const float* __restrict__ Ain, const float* __restrict__ DW,
    float* __restrict__ out, int e, int cnt, int m0, int n0)
{
    __shared__ uint32_t As[2][2048];
    __shared__ uint32_t Bs[2][2048];

    int tid = threadIdx.x;
    int lane = tid & 31, wid = tid >> 5;
    int gid = lane >> 2, tig = lane & 3;
    int wm = (wid & 3) * 32;
    int wn = (wid >> 2) * 64;

    int lr = tid >> 1;
    int lks = tid & 1;
    int arow = m0 + lr;
    if (ROUTED) { if (arow >= cnt) arow = cnt - 1; }
    const float* aptr = Ain + (size_t)arow * KDIM + lks * 8;
    const float* bptr = DW + (size_t)(n0 + lr) * KDIM + lks * 8;

    {
        float4 va0 = *(const float4*)(aptr + 0);
        float4 va1 = *(const float4*)(aptr + 4);
        float4 vb0 = *(const float4*)(bptr + 0);
        float4 vb1 = *(const float4*)(bptr + 4);
        stsA_frag(As[0], lr, lks, va0, va1);
        stsB_frag8(Bs[0], lr, lks, vb0, vb1);
    }
    __syncthreads();

    float acc[2][8][4] = {{{0}}};

    const int NIT = KDIM / 16;
    for (int it = 0; it < NIT; it++) {
        int b = it & 1;
        bool more = (it + 1 < NIT);
        float4 va0, va1, vb0, vb1;
        if (more) {
            int kb = (it + 1) * 16;
            va0 = *(const float4*)(aptr + kb);
            va1 = *(const float4*)(aptr + kb + 4);
            vb0 = *(const float4*)(bptr + kb);
            vb1 = *(const float4*)(bptr + kb + 4);
        }
        uint32_t a[2][2][4];
        #pragma unroll
        for (int mt = 0; mt < 2; mt++) {
            int t = (wid & 3) * 2 + mt;
            #pragma unroll
            for (int ks = 0; ks < 2; ks++) {
                uint4 av = ldA_frag(As[b], t, ks, gid, tig);
                a[mt][ks][0] = av.x; a[mt][ks][1] = av.y;
                a[mt][ks][2] = av.z; a[mt][ks][3] = av.w;
            }
        }
        #pragma unroll
        for (int nt = 0; nt < 8; nt++) {
            int c = wn + nt * 8 + gid;
            uint4 bv = ldB_frag(Bs[b], c, tig);
            mma8(acc[0][nt], a[0][0], bv.x, bv.y);
            mma8(acc[1][nt], a[1][0], bv.x, bv.y);
            mma8(acc[0][nt], a[0][1], bv.z, bv.w);
            mma8(acc[1][nt], a[1][1], bv.z, bv.w);
        }
        if (more) {
            int nb = (it + 1) & 1;
            stsA_frag(As[nb], lr, lks, va0, va1);
            stsB_frag8(Bs[nb], lr, lks, vb0, vb1);
        }
        __syncthreads();
    }

    #pragma unroll
    for (int mt = 0; mt < 2; mt++) {
        #pragma unroll
        for (int half = 0; half < 2; half++) {
            int r = m0 + wm + mt * 16 + gid + half * 8;
            float wt = 1.f;
            float* op;
            if (ROUTED) {
                if (r >= cnt) continue;
                int tok = g_tok[e * T_TOK + r];
                wt = g_wt[e * T_TOK + r];
                op = out + (size_t)tok * H_DIM;
            } else {
                op = out + (size_t)r * H_DIM;
            }
            #pragma unroll
            for (int nt = 0; nt < 8; nt++) {
                int cb = n0 + wn + nt * 8 + 2 * tig;
                atomicAdd(&op[cb    ], acc[mt][nt][half * 2    ] * wt);
                atomicAdd(&op[cb + 1], acc[mt][nt][half * 2 + 1] * wt);
            }
        }
    }
}

// Merged down: blocks [0,128) = shared, [128, 128+8*nmb) = routed.
__global__ __launch_bounds__(256, 2)
void down_all(const float* __restrict__ DW, const float* __restrict__ SDW,
              float* __restrict__ out) {
    int bid = blockIdx.x;
    if (bid < 128) {
        int m0 = (bid >> 3) * 128;
        int n0 = (bid & 7) * 128;
        down_body<SH_I, false>(g_hidden_sh, SDW, out, 0, T_TOK, m0, n0);
    } else {
        int rb = bid - 128;
        int mb = rb >> 3;
        if (mb >= g_nmb) return;
        int e   = g_sched_e[mb];
        int m0  = g_sched_m[mb];
        int cnt = g_counts[e];
        int n0  = (rb & 7) * 128;
        down_body<I_DIM, true>(g_hidden + (size_t)e * T_TOK * I_DIM,
                               DW + (size_t)e * H_DIM * I_DIM, out, e, cnt, m0, n0);
    }
}

// ---------------------------------------------------------------------------
extern "C" void kernel_launch(void* const* d_in, const int* in_sizes, int n_in,
                              void* d_out, int out_size) {
    const float* hs  = (const float*)d_in[0];
    const float* rw  = (const float*)d_in[1];
    const float* rb  = (const float*)d_in[2];
    const float* gw  = (const float*)d_in[3];
    const float* uw  = (const float*)d_in[4];
    const float* dw  = (const float*)d_in[5];
    const float* sgw = (const float*)d_in[6];
    const float* suw = (const float*)d_in[7];
    const float* sdw = (const float*)d_in[8];
    float* out = (float*)d_out;

    zero_counts_kernel<<<1, 32>>>();
    router_kernel<<<T_TOK / 4, 128>>>(hs, rw, rb);
    sched_kernel<<<1, 32>>>();
    zero_out_kernel<<<(T_TOK * H_DIM / 4) / 256, 256>>>(out);

    gateup_all<<<256 + 8 * MAXMB, 256>>>(hs, gw, uw, sgw, suw);
    down_all  <<<128 + 8 * MAXMB, 256>>>(dw, sdw, out);
}

// round 7
// speedup vs baseline: 2.1199x; 1.0720x over previous
#include <cuda_runtime.h>
#include <cuda_bf16.h>
#include <math.h>
#include <stdint.h>

#define T_TOK   2048
#define H_DIM   1024
#define I_DIM   512
#define N_EXP   32
#define TOP_K   4
#define N_GROUP 4
#define GRP_SZ  8
#define SCALE   2.5f
#define SH_I    1024
#define MAXMB   96

// 4-stage cp.async pipeline, BK=16, rows stored with stride 20 words (conflict-free)
#define STAGES  4
#define RS      20                 // row stride in words
#define A_STG   2560               // 128 rows * 20 words
#define B_STG   2560               // down: 128 rows
#define G_STG   1280               // gateup: 64 rows
#define SMEM_WORDS 20480           // 4*(2560+2560) == 4*(2560+1280+1280)
#define SMEM_BYTES (SMEM_WORDS * 4)

// ---------------- scratch ----------------------------------------------------
__device__ float g_hidden[(size_t)N_EXP * T_TOK * I_DIM];
__device__ float g_hidden_sh[(size_t)T_TOK * SH_I];
__device__ int   g_counts[N_EXP];
__device__ int   g_tok[N_EXP * T_TOK];
__device__ float g_wt[N_EXP * T_TOK];
__device__ int   g_nmb;
__device__ int   g_sched_e[MAXMB];
__device__ int   g_sched_m[MAXMB];

// ---------------- helpers ----------------------------------------------------
__device__ __forceinline__ uint32_t f2tf(float x) {
    uint32_t r; asm("cvt.rna.tf32.f32 %0, %1;" : "=r"(r) : "f"(x)); return r;
}
__device__ __forceinline__ uint32_t w2tf(uint32_t w) { return f2tf(__uint_as_float(w)); }
__device__ __forceinline__ void mma8(float* c, const uint32_t* a, uint32_t b0, uint32_t b1) {
    asm volatile("mma.sync.aligned.m16n8k8.row.col.f32.tf32.tf32.f32 "
        "{%0,%1,%2,%3}, {%4,%5,%6,%7}, {%8,%9}, {%0,%1,%2,%3};\n"
        : "+f"(c[0]), "+f"(c[1]), "+f"(c[2]), "+f"(c[3])
        : "r"(a[0]), "r"(a[1]), "r"(a[2]), "r"(a[3]), "r"(b0), "r"(b1));
}
__device__ __forceinline__ uint32_t smem_u32(const void* p) {
    uint32_t a;
    asm("{ .reg .u64 t; cvta.to.shared.u64 t, %1; cvt.u32.u64 %0, t; }" : "=r"(a) : "l"(p));
    return a;
}
__device__ __forceinline__ void cpa16(uint32_t dst, const float* src) {
    asm volatile("cp.async.cg.shared.global [%0], [%1], 16;" :: "r"(dst), "l"(src));
}
#define CPA_COMMIT() asm volatile("cp.async.commit_group;" ::: "memory")
#define CPA_WAIT2()  asm volatile("cp.async.wait_group 2;"  ::: "memory")

// ---------------------------------------------------------------------------
__global__ void zero_counts_kernel() {
    if (threadIdx.x < N_EXP) g_counts[threadIdx.x] = 0;
}
__global__ void zero_out_kernel(float* __restrict__ out) {
    int i = blockIdx.x * blockDim.x + threadIdx.x;
    ((float4*)out)[i] = make_float4(0.f, 0.f, 0.f, 0.f);
}

__global__ void router_kernel(const float* __restrict__ hs,
                              const float* __restrict__ rw,
                              const float* __restrict__ rb) {
    int warp = threadIdx.x >> 5;
    int lane = threadIdx.x & 31;
    int t = blockIdx.x * (blockDim.x >> 5) + warp;
    if (t >= T_TOK) return;

    const float* x = hs + (size_t)t * H_DIM;
    const float* w = rw + (size_t)lane * H_DIM;

    float a0 = 0.f, a1 = 0.f, a2 = 0.f, a3 = 0.f;
    #pragma unroll 4
    for (int h = 0; h < H_DIM; h += 4) {
        a0 = fmaf(x[h + 0], w[h + 0], a0);
        a1 = fmaf(x[h + 1], w[h + 1], a1);
        a2 = fmaf(x[h + 2], w[h + 2], a2);
        a3 = fmaf(x[h + 3], w[h + 3], a3);
    }
    float logit = (a0 + a1) + (a2 + a3);
    float score = 1.f / (1.f + expf(-logit));
    float sfc   = score + rb[lane];

    float s[N_EXP], sc[N_EXP];
    #pragma unroll
    for (int e = 0; e < N_EXP; e++) {
        s[e]  = __shfl_sync(0xffffffffu, sfc, e);
        sc[e] = __shfl_sync(0xffffffffu, score, e);
    }

    if (lane == 0) {
        float gsc[N_GROUP];
        #pragma unroll
        for (int g = 0; g < N_GROUP; g++) {
            float m1 = -1e30f, m2 = -1e30f;
            #pragma unroll
            for (int j = 0; j < GRP_SZ; j++) {
                float v = s[g * GRP_SZ + j];
                if (v > m1) { m2 = m1; m1 = v; }
                else if (v > m2) { m2 = v; }
            }
            gsc[g] = m1 + m2;
        }
        int g1 = 0;
        #pragma unroll
        for (int g = 1; g < N_GROUP; g++) if (gsc[g] > gsc[g1]) g1 = g;
        int g2 = -1;
        #pragma unroll
        for (int g = 0; g < N_GROUP; g++) {
            if (g == g1) continue;
            if (g2 < 0 || gsc[g] > gsc[g2]) g2 = g;
        }
        float v[N_EXP];
        #pragma unroll
        for (int e = 0; e < N_EXP; e++) {
            int g = e / GRP_SZ;
            v[e] = (g == g1 || g == g2) ? s[e] : -1e30f;
        }
        int   idx[TOP_K];
        float wsum = 0.f;
        #pragma unroll
        for (int k = 0; k < TOP_K; k++) {
            int b = 0;
            #pragma unroll
            for (int e = 1; e < N_EXP; e++) if (v[e] > v[b]) b = e;
            idx[k] = b;
            v[b] = -2e30f;
            wsum += sc[b];
        }
        float inv = SCALE / (wsum + 1e-20f);
        #pragma unroll
        for (int k = 0; k < TOP_K; k++) {
            int e = idx[k];
            int p = atomicAdd(&g_counts[e], 1);
            g_tok[e * T_TOK + p] = t;
            g_wt [e * T_TOK + p] = sc[e] * inv;
        }
    }
}

__global__ void sched_kernel() {
    int lane = threadIdx.x;
    int cnt = (lane < N_EXP) ? g_counts[lane] : 0;
    int nb = (cnt + 127) >> 7;
    int incl = nb;
    #pragma unroll
    for (int off = 1; off < 32; off <<= 1) {
        int v = __shfl_up_sync(0xffffffffu, incl, off);
        if (lane >= off) incl += v;
    }
    int base = incl - nb;
    for (int j = 0; j < nb; j++) {
        g_sched_e[base + j] = lane;
        g_sched_m[base + j] = j * 128;
    }
    if (lane == 31) g_nmb = incl;
}

// ---------------------------------------------------------------------------
// Gate+up body: CTA M=128, N=64/matrix, 8 warps 4m x 2n, 4-stage cp.async.
template <bool ROUTED>
__device__ __forceinline__ void gateup_body(
    const float* __restrict__ X, const float* __restrict__ GW,
    const float* __restrict__ UW, float* __restrict__ H_out,
    int e, int cnt, int m0, int n0, int ldh)
{
    extern __shared__ uint32_t dsm[];
    uint32_t sb = smem_u32(dsm);

    int tid = threadIdx.x;
    int lane = tid & 31, wid = tid >> 5;
    int gid = lane >> 2, tig = lane & 3;
    int wm = (wid & 3) * 32;
    int wn = (wid >> 2) * 32;

    // loaders
    int lr = tid >> 1, lh = tid & 1;          // A: row, 8-word half
    int ar = m0 + lr;
    if (ROUTED) { if (ar >= cnt) ar = cnt - 1; }
    const float* aptr = (ROUTED ? X + (size_t)g_tok[e * T_TOK + ar] * H_DIM
                                : X + (size_t)ar * H_DIM) + lh * 8;
    int gr = tid >> 2, gq = tid & 3;          // G/U: row, 4-word quarter
    const float* gptr = GW + (size_t)(n0 + gr) * H_DIM + gq * 4;
    const float* uptr = UW + (size_t)(n0 + gr) * H_DIM + gq * 4;

    uint32_t dA = sb + (lr * RS + lh * 8) * 4;
    uint32_t dG = sb + (STAGES * A_STG + gr * RS + gq * 4) * 4;
    uint32_t dU = dG + STAGES * G_STG * 4;

    #pragma unroll
    for (int s = 0; s < 3; s++) {
        int k0 = s * 16;
        cpa16(dA + s * A_STG * 4,      aptr + k0);
        cpa16(dA + s * A_STG * 4 + 16, aptr + k0 + 4);
        cpa16(dG + s * G_STG * 4,      gptr + k0);
        cpa16(dU + s * G_STG * 4,      uptr + k0);
        CPA_COMMIT();
    }

    float accG[2][4][4] = {{{0}}};
    float accU[2][4][4] = {{{0}}};

    const int NIT = H_DIM / 16;   // 64
    for (int it = 0; it < NIT; it++) {
        CPA_WAIT2();
        __syncthreads();
        int s = it & 3;
        const uint32_t* As = dsm + s * A_STG;
        const uint32_t* Gs = dsm + STAGES * A_STG + s * G_STG;
        const uint32_t* Us = dsm + STAGES * A_STG + STAGES * G_STG + s * G_STG;

        uint32_t a[2][2][4];
        #pragma unroll
        for (int mt = 0; mt < 2; mt++) {
            int r0 = wm + mt * 16 + gid;
            #pragma unroll
            for (int ks = 0; ks < 2; ks++) {
                int base = r0 * RS + ks * 8 + tig;
                a[mt][ks][0] = w2tf(As[base]);
                a[mt][ks][1] = w2tf(As[base + 8 * RS]);
                a[mt][ks][2] = w2tf(As[base + 4]);
                a[mt][ks][3] = w2tf(As[base + 8 * RS + 4]);
            }
        }
        #pragma unroll
        for (int nt = 0; nt < 4; nt++) {
            int c = wn + nt * 8 + gid;
            #pragma unroll
            for (int ks = 0; ks < 2; ks++) {
                int cb = c * RS + ks * 8 + tig;
                uint32_t g0 = w2tf(Gs[cb]), g1 = w2tf(Gs[cb + 4]);
                uint32_t u0 = w2tf(Us[cb]), u1 = w2tf(Us[cb + 4]);
                mma8(accG[0][nt], a[0][ks], g0, g1);
                mma8(accG[1][nt], a[1][ks], g0, g1);
                mma8(accU[0][nt], a[0][ks], u0, u1);
                mma8(accU[1][nt], a[1][ks], u0, u1);
            }
        }
        int nx = it + 3;
        if (nx < NIT) {
            int ns = nx & 3;
            int k0 = nx * 16;
            cpa16(dA + ns * A_STG * 4,      aptr + k0);
            cpa16(dA + ns * A_STG * 4 + 16, aptr + k0 + 4);
            cpa16(dG + ns * G_STG * 4,      gptr + k0);
            cpa16(dU + ns * G_STG * 4,      uptr + k0);
        }
        CPA_COMMIT();
    }

    #pragma unroll
    for (int mt = 0; mt < 2; mt++) {
        #pragma unroll
        for (int half = 0; half < 2; half++) {
            int r = m0 + wm + mt * 16 + gid + half * 8;
            if (ROUTED && r >= cnt) continue;
            #pragma unroll
            for (int nt = 0; nt < 4; nt++) {
                int cb = n0 + wn + nt * 8 + 2 * tig;
                #pragma unroll
                for (int j = 0; j < 2; j++) {
                    float g = accG[mt][nt][half * 2 + j];
                    float u = accU[mt][nt][half * 2 + j];
                    float sil = g / (1.f + expf(-g));
                    H_out[(size_t)r * ldh + cb + j] = sil * u;
                }
            }
        }
    }
}

__global__ __launch_bounds__(256, 2)
void gateup_all(const float* __restrict__ X,
                const float* __restrict__ GW, const float* __restrict__ UW,
                const float* __restrict__ SGW, const float* __restrict__ SUW) {
    int bid = blockIdx.x;
    if (bid < 256) {
        int m0 = (bid >> 4) * 128;
        int n0 = (bid & 15) * 64;
        gateup_body<false>(X, SGW, SUW, g_hidden_sh, 0, T_TOK, m0, n0, SH_I);
    } else {
        int rb = bid - 256;
        int mb = rb >> 3;
        if (mb >= g_nmb) return;
        int e   = g_sched_e[mb];
        int m0  = g_sched_m[mb];
        int cnt = g_counts[e];
        int n0  = (rb & 7) * 64;
        gateup_body<true>(X, GW + (size_t)e * I_DIM * H_DIM,
                          UW + (size_t)e * I_DIM * H_DIM,
                          g_hidden + (size_t)e * T_TOK * I_DIM,
                          e, cnt, m0, n0, I_DIM);
    }
}

// ---------------------------------------------------------------------------
// Down body: CTA M=128, N=128, warp 32x64, 4-stage cp.async. atomicAdd epilogue.
template <int KDIM, bool ROUTED>
__device__ __forceinline__ void down_body(
    const float* __restrict__ Ain, const float* __restrict__ DW,
    float* __restrict__ out, int e, int cnt, int m0, int n0)
{
    extern __shared__ uint32_t dsm[];
    uint32_t sb = smem_u32(dsm);

    int tid = threadIdx.x;
    int lane = tid & 31, wid = tid >> 5;
    int gid = lane >> 2, tig = lane & 3;
    int wm = (wid & 3) * 32;
    int wn = (wid >> 2) * 64;

    int lr = tid >> 1, lh = tid & 1;
    int ar = m0 + lr;
    if (ROUTED) { if (ar >= cnt) ar = cnt - 1; }
    const float* aptr = Ain + (size_t)ar * KDIM + lh * 8;
    const float* bptr = DW + (size_t)(n0 + lr) * KDIM + lh * 8;

    uint32_t dA = sb + (lr * RS + lh * 8) * 4;
    uint32_t dB = sb + (STAGES * A_STG + lr * RS + lh * 8) * 4;

    #pragma unroll
    for (int s = 0; s < 3; s++) {
        int k0 = s * 16;
        cpa16(dA + s * A_STG * 4,      aptr + k0);
        cpa16(dA + s * A_STG * 4 + 16, aptr + k0 + 4);
        cpa16(dB + s * B_STG * 4,      bptr + k0);
        cpa16(dB + s * B_STG * 4 + 16, bptr + k0 + 4);
        CPA_COMMIT();
    }

    float acc[2][8][4] = {{{0}}};

    const int NIT = KDIM / 16;
    for (int it = 0; it < NIT; it++) {
        CPA_WAIT2();
        __syncthreads();
        int s = it & 3;
        const uint32_t* As = dsm + s * A_STG;
        const uint32_t* Bs = dsm + STAGES * A_STG + s * B_STG;

        uint32_t a[2][2][4];
        #pragma unroll
        for (int mt = 0; mt < 2; mt++) {
            int r0 = wm + mt * 16 + gid;
            #pragma unroll
            for (int ks = 0; ks < 2; ks++) {
                int base = r0 * RS + ks * 8 + tig;
                a[mt][ks][0] = w2tf(As[base]);
                a[mt][ks][1] = w2tf(As[base + 8 * RS]);
                a[mt][ks][2] = w2tf(As[base + 4]);
                a[mt][ks][3] = w2tf(As[base + 8 * RS + 4]);
            }
        }
        #pragma unroll
        for (int nt = 0; nt < 8; nt++) {
            int c = wn + nt * 8 + gid;
            #pragma unroll
            for (int ks = 0; ks < 2; ks++) {
                int cb = c * RS + ks * 8 + tig;
                uint32_t b0 = w2tf(Bs[cb]), b1 = w2tf(Bs[cb + 4]);
                mma8(acc[0][nt], a[0][ks], b0, b1);
                mma8(acc[1][nt], a[1][ks], b0, b1);
            }
        }
        int nx = it + 3;
        if (nx < NIT) {
            int ns = nx & 3;
            int k0 = nx * 16;
            cpa16(dA + ns * A_STG * 4,      aptr + k0);
            cpa16(dA + ns * A_STG * 4 + 16, aptr + k0 + 4);
            cpa16(dB + ns * B_STG * 4,      bptr + k0);
            cpa16(dB + ns * B_STG * 4 + 16, bptr + k0 + 4);
        }
        CPA_COMMIT();
    }

    #pragma unroll
    for (int mt = 0; mt < 2; mt++) {
        #pragma unroll
        for (int half = 0; half < 2; half++) {
            int r = m0 + wm + mt * 16 + gid + half * 8;
            float wt = 1.f;
            float* op;
            if (ROUTED) {
                if (r >= cnt) continue;
                int tok = g_tok[e * T_TOK + r];
                wt = g_wt[e * T_TOK + r];
                op = out + (size_t)tok * H_DIM;
            } else {
                op = out + (size_t)r * H_DIM;
            }
            #pragma unroll
            for (int nt = 0; nt < 8; nt++) {
                int cb = n0 + wn + nt * 8 + 2 * tig;
                atomicAdd(&op[cb    ], acc[mt][nt][half * 2    ] * wt);
                atomicAdd(&op[cb + 1], acc[mt][nt][half * 2 + 1] * wt);
            }
        }
    }
}

__global__ __launch_bounds__(256, 2)
void down_all(const float* __restrict__ DW, const float* __restrict__ SDW,
              float* __restrict__ out) {
    int bid = blockIdx.x;
    if (bid < 128) {
        int m0 = (bid >> 3) * 128;
        int n0 = (bid & 7) * 128;
        down_body<SH_I, false>(g_hidden_sh, SDW, out, 0, T_TOK, m0, n0);
    } else {
        int rb = bid - 128;
        int mb = rb >> 3;
        if (mb >= g_nmb) return;
        int e   = g_sched_e[mb];
        int m0  = g_sched_m[mb];
        int cnt = g_counts[e];
        int n0  = (rb & 7) * 128;
        down_body<I_DIM, true>(g_hidden + (size_t)e * T_TOK * I_DIM,
                               DW + (size_t)e * H_DIM * I_DIM, out, e, cnt, m0, n0);
    }
}

// ---------------------------------------------------------------------------
extern "C" void kernel_launch(void* const* d_in, const int* in_sizes, int n_in,
                              void* d_out, int out_size) {
    const float* hs  = (const float*)d_in[0];
    const float* rw  = (const float*)d_in[1];
    const float* rb  = (const float*)d_in[2];
    const float* gw  = (const float*)d_in[3];
    const float* uw  = (const float*)d_in[4];
    const float* dw  = (const float*)d_in[5];
    const float* sgw = (const float*)d_in[6];
    const float* suw = (const float*)d_in[7];
    const float* sdw = (const float*)d_in[8];
    float* out = (float*)d_out;

    cudaFuncSetAttribute(gateup_all, cudaFuncAttributeMaxDynamicSharedMemorySize, SMEM_BYTES);
    cudaFuncSetAttribute(down_all,   cudaFuncAttributeMaxDynamicSharedMemorySize, SMEM_BYTES);

    zero_counts_kernel<<<1, 32>>>();
    router_kernel<<<T_TOK / 4, 128>>>(hs, rw, rb);
    sched_kernel<<<1, 32>>>();
    zero_out_kernel<<<(T_TOK * H_DIM / 4) / 256, 256>>>(out);

    gateup_all<<<256 + 8 * MAXMB, 256, SMEM_BYTES>>>(hs, gw, uw, sgw, suw);
    down_all  <<<128 + 8 * MAXMB, 256, SMEM_BYTES>>>(dw, sdw, out);
}